// round 6
// baseline (speedup 1.0000x reference)
#include <cuda_runtime.h>

#define NQ 16
#define BATCH 512

// Transfer-matrix chains in trace/traceless basis (p, q, R=2r, S2=2s).
// Per-wire step:  hp = p + wx2*R        hq = nd*q - wy2*S2
//                 hr = wx2*p + R        hs = wy2*q + nd*S2
//                 p' = a*hp + b*hq      q' = b*hp + a*hq
//                 R' = m01*hr           S2' = m01*hs
// signed:  a=0, b=C, m01=-S    unsigned: a=1, b=0, m01=0
__global__ void __launch_bounds__(160) k_expval(const float* __restrict__ x,
                                                const float* __restrict__ p_,
                                                float* __restrict__ out) {
    __shared__ float2 sX[4][NQ];   // (cos x, sin x) per sample-in-block, wire
    __shared__ float2 sP0[NQ];     // (cos th0, sin th0)
    __shared__ float2 sP1[NQ];     // (cos th1, sin th1)

    const int tid = threadIdx.x;

    // ---- prologue: one sincos per thread ----
    if (tid < 64) {
        const int w  = tid & 15;
        const int bl = tid >> 4;
        const int b  = blockIdx.x * 4 + bl;
        float s, c; __sincosf(x[b * NQ + w], &s, &c);
        sX[bl][w] = make_float2(c, s);
    } else if (tid < 96) {
        const int j = tid - 64;          // 0..31
        float s, c; __sincosf(p_[j], &s, &c);
        if (j < 16) sP0[j]      = make_float2(c, s);
        else        sP1[j - 16] = make_float2(c, s);
    }
    __syncthreads();

    // ---- chain assignment (layout identical to rounds 4/5) ----
    int bl = tid / 36;
    const int cid = tid - bl * 36;
    if (bl > 3) bl = 3;
    const bool pad = (tid >= 144);

    const int m    = (cid < 28) ? (1 + (cid >> 1)) : ((cid < 32) ? 0 : 15);
    const int meff = (cid < 28) ? m : 15;
    const int typ  = (cid < 28) ? (cid & 1) : (cid & 3);

    // wire-0 derived constants
    const float2 X0 = sX[bl][0];
    const float2 A0 = sP0[0];
    const float2 G0 = sP1[0];
    const float nd0  = A0.x * X0.x;     // cos th0 * cos x
    const float wx20 = A0.y * X0.x;     // sin th0 * cos x
    const float sx0  = X0.y;

    // ---- init + readout selector ----
    float p = 0.f, q = 0.f, R = 0.f, S2 = 0.f;
    int sel;                             // 0:p 1:q 2:R 3:-S2 4:zero
    if (cid < 28) {
        if (typ == 0) { p = G0.x * nd0;  q = G0.x;        sel = 1; }
        else          { R = -G0.y * wx20; S2 = -G0.y * sx0; sel = 0; }
    } else if (cid < 32) {               // m = 0 (wire 0 unsigned)
        if      (typ == 0) { p = 1.f; q = nd0;           sel = 0; }
        else if (typ == 1) { R = wx20; S2 = sx0;         sel = 2; }
        else               {                              sel = 4; }
    } else {                             // m = 15 (wire 0 signed)
        if      (typ == 0) { p = G0.x * nd0;  q = G0.x;          sel = 1; }
        else if (typ == 1) { R = -G0.y * wx20; S2 = -G0.y * sx0; sel = 0; }
        else if (typ == 2) { p = -G0.y; q = -G0.y * nd0;         sel = 2; }
        else               { R = G0.x * sx0; S2 = -G0.x * wx20;  sel = 3; }
    }

    // ---- wires 1..15 ----
    #pragma unroll
    for (int w = 1; w < NQ; w++) {
        const float2 X = sX[bl][w];
        const float2 A = sP0[w];
        const float2 G = sP1[w];
        const float nd  = A.x * X.x;
        const float wx2 = A.y * X.x;
        const float wy2 = X.y;
        const bool  sg  = (w <= meff);
        const float al  = sg ? 0.f  : 1.f;
        const float be  = sg ? G.x  : 0.f;
        const float m01 = sg ? -G.y : 0.f;

        const float hp = fmaf(wx2, R, p);
        const float hq = fmaf(nd, q, -wy2 * S2);
        const float hr = fmaf(wx2, p, R);
        const float hs = fmaf(wy2, q, nd * S2);
        p  = fmaf(be, hq, al * hp);
        q  = fmaf(be, hp, al * hq);
        R  = m01 * hr;
        S2 = m01 * hs;
    }

    // ---- readout + reductions (same pattern as rounds 4/5) ----
    float val;
    switch (sel) {
        case 0:  val = p;   break;
        case 1:  val = q;   break;
        case 2:  val = R;   break;
        case 3:  val = -S2; break;
        default: val = 0.f; break;
    }

    const float v1s = val + __shfl_xor_sync(0xFFFFFFFFu, val, 1);
    const float v2s = v1s + __shfl_xor_sync(0xFFFFFFFFu, v1s, 2);

    if (!pad) {
        const int b = blockIdx.x * 4 + bl;
        if (cid < 28) {
            if ((cid & 1) == 0) out[b * NQ + m] = v1s;
        } else {
            if ((cid & 3) == 0) out[b * NQ + m] = v2s;
        }
    }
}

extern "C" void kernel_launch(void* const* d_in, const int* in_sizes, int n_in,
                              void* d_out, int out_size) {
    (void)in_sizes; (void)n_in; (void)out_size;
    const float* x      = (const float*)d_in[0];
    const float* params = (const float*)d_in[1];
    float* out = (float*)d_out;

    k_expval<<<128, 160>>>(x, params, out);
}

// round 7
// speedup vs baseline: 1.0435x; 1.0435x over previous
#include <cuda_runtime.h>

#define NQ 16
#define BATCH 512

// Warp-autonomous transfer-matrix evaluation: 1 warp = 1 sample, no smem,
// no __syncthreads. Constants broadcast by shuffles; 2 chains per lane.
//
// Step (trace/traceless basis, validated rounds 5-6):
//   hp = p + wx2*R      hq = nd*q - wy2*S2
//   hr = wx2*p + R      hs = wy2*q + nd*S2
//   p' = al*hp + be*hq  q' = be*hp + al*hq   R' = m01*hr   S2' = m01*hs
//   signed: al=0, be=C, m01=-S     unsigned: al=1, be=0, m01=0
__global__ void __launch_bounds__(128) k_expval(const float* __restrict__ x,
                                                const float* __restrict__ p_,
                                                float* __restrict__ out) {
    const int lane = threadIdx.x & 31;
    const int b    = (blockIdx.x << 2) + (threadIdx.x >> 5);   // sample

    // ---- per-lane constants ----
    // lanes 0..15: wire = lane; hold nd, wx2, wy2
    // lanes 16..31: wire = lane-16; hold C, S (theta1)
    float vA, vB, vC;          // nd, wx2, wy2   (lanes < 16)
    float vD, vE;              // C, S           (lanes >= 16)
    {
        const float pw = p_[lane];                 // th0 (lane<16) or th1 (lane>=16)
        float sp, cp; __sincosf(pw, &sp, &cp);
        if (lane < 16) {
            float sx, cx; __sincosf(x[b * NQ + lane], &sx, &cx);
            vA = cp * cx;      // nd  = cos th0 * cos x
            vB = sp * cx;      // wx2 = sin th0 * cos x
            vC = sx;           // wy2 = sin x
            vD = 0.f; vE = 0.f;
        } else {
            vD = cp; vE = sp;
            vA = 0.f; vB = 0.f; vC = 0.f;
        }
    }

    // ---- chain assignment ----
    // lanes 0..13 : m = lane+1   (diag pair: chainA read q, chainB read p)
    // lane 14     : m = 0        (chainA read p, chainB read R)
    // lane 15     : m = 15 first half (chainA read q, chainB read p)
    // lanes 16..31: m = 15 second half (chainA read R, chainB read -S2);
    //               only lane 31's value is used (combined with lane 15)
    const int  meff  = (lane >= 14) ? 15 : (lane + 1);   // last signed wire
    const bool isM0  = (lane == 14);
    const bool isHi  = (lane >= 16);

    // wire-0 constants (broadcast)
    const float nd0  = __shfl_sync(0xFFFFFFFFu, vA, 0);
    const float wx20 = __shfl_sync(0xFFFFFFFFu, vB, 0);
    const float sx0  = __shfl_sync(0xFFFFFFFFu, vC, 0);
    const float C0   = __shfl_sync(0xFFFFFFFFu, vD, 16);
    const float S0   = __shfl_sync(0xFFFFFFFFu, vE, 16);

    // ---- wire-0 init ----
    float pA, qA, RA, SA, pB, qB, RB, SB;
    if (isM0) {              // wire 0 unsigned
        pA = 1.f;        qA = nd0;        RA = 0.f;        SA = 0.f;
        pB = 0.f;        qB = 0.f;        RB = wx20;       SB = sx0;
    } else if (isHi) {       // m=15, typ2 / typ3 chains
        pA = -S0;        qA = -S0 * nd0;  RA = 0.f;        SA = 0.f;
        pB = 0.f;        qB = 0.f;        RB = C0 * sx0;   SB = -C0 * wx20;
    } else {                 // m>=1 diag chains (wire 0 signed)
        pA = C0 * nd0;   qA = C0;         RA = 0.f;        SA = 0.f;
        pB = 0.f;        qB = 0.f;        RB = -S0 * wx20; SB = -S0 * sx0;
    }

    // ---- wires 1..15 ----
    #pragma unroll
    for (int w = 1; w < NQ; w++) {
        const float nd  = __shfl_sync(0xFFFFFFFFu, vA, w);
        const float wx2 = __shfl_sync(0xFFFFFFFFu, vB, w);
        const float wy2 = __shfl_sync(0xFFFFFFFFu, vC, w);
        const float C   = __shfl_sync(0xFFFFFFFFu, vD, 16 + w);
        const float S   = __shfl_sync(0xFFFFFFFFu, vE, 16 + w);

        const bool  sg  = (w <= meff);
        const float al  = sg ? 0.f : 1.f;
        const float be  = sg ? C   : 0.f;
        const float m01 = sg ? -S  : 0.f;

        {   // chain A
            const float hp = fmaf(wx2, RA, pA);
            const float hq = fmaf(nd, qA, -wy2 * SA);
            const float hr = fmaf(wx2, pA, RA);
            const float hs = fmaf(wy2, qA, nd * SA);
            pA = fmaf(be, hq, al * hp);
            qA = fmaf(be, hp, al * hq);
            RA = m01 * hr;
            SA = m01 * hs;
        }
        {   // chain B
            const float hp = fmaf(wx2, RB, pB);
            const float hq = fmaf(nd, qB, -wy2 * SB);
            const float hr = fmaf(wx2, pB, RB);
            const float hs = fmaf(wy2, qB, nd * SB);
            pB = fmaf(be, hq, al * hp);
            qB = fmaf(be, hp, al * hq);
            RB = m01 * hr;
            SB = m01 * hs;
        }
    }

    // ---- readout ----
    const float valA = isM0 ? pA : (isHi ? RA : qA);
    const float valB = isM0 ? RB : (isHi ? -SB : pB);
    float val = valA + valB;

    // combine m=15 halves (lane 15 <- lane 31)
    val += (lane == 15 || lane == 31) ? __shfl_xor_sync(0xFFFFFFFFu, val, 16)
                                      : 0.f;

    if (lane < 16) {
        const int m = (lane < 14) ? (lane + 1) : ((lane == 14) ? 0 : 15);
        out[b * NQ + m] = val;
    }
}

extern "C" void kernel_launch(void* const* d_in, const int* in_sizes, int n_in,
                              void* d_out, int out_size) {
    (void)in_sizes; (void)n_in; (void)out_size;
    const float* x      = (const float*)d_in[0];
    const float* params = (const float*)d_in[1];
    float* out = (float*)d_out;

    k_expval<<<128, 128>>>(x, params, out);
}